// round 2
// baseline (speedup 1.0000x reference)
#include <cuda_runtime.h>
#include <cstdint>

#define CI  256   // channels
#define II  16    // irrep dim
#define NK3 23
#define NK2 4
#define NT3 816   // C(18,3) sorted triples p<=q<=j (compact)
#define NT3P 888  // padded (each (p,q)-run rounded to even length)
#define NT2 136   // sorted pairs p<=q
#define CSTRIDE 1056  // per-channel coeff stride in ull: [c3:888][c2:136][c1:16] + pad
#define BMAX 4096

// ---------------- static device scratch (no allocation allowed) ----------------
__device__ float              g_P[NT3 * NK3];            // symmetrized U3 basis
__device__ unsigned long long g_coeff[CI * CSTRIDE];     // per-channel packed (v,v) coeffs
__device__ float              g_out1[BMAX * CI];         // (B, C) intermediate

typedef unsigned long long ull;

// ---------------- f32x2 packed-math helpers (sm_103a FFMA2 path) ----------------
__device__ __forceinline__ ull pk2(float lo, float hi) {
    ull r;
    asm("mov.b64 %0, {%1, %2};" : "=l"(r) : "f"(lo), "f"(hi));
    return r;
}
__device__ __forceinline__ void upk2(ull v, float& lo, float& hi) {
    asm("mov.b64 {%0, %1}, %2;" : "=f"(lo), "=f"(hi) : "l"(v));
}
__device__ __forceinline__ ull fma2(ull a, ull b, ull c) {
    ull d;
    asm("fma.rn.f32x2 %0, %1, %2, %3;" : "=l"(d) : "l"(a), "l"(b), "l"(c));
    return d;
}
__device__ __forceinline__ ull mul2(ull a, ull b) {
    ull d;
    asm("mul.rn.f32x2 %0, %1, %2;" : "=l"(d) : "l"(a), "l"(b));
    return d;
}

// ---------------- P0: symmetrize U3 over permutations -> g_P[t][k] ----------------
#define U3AT(a, b, d) U3[((((a) * II + (b)) * II + (d)) * NK3) + k]

__global__ void p0_kernel(const float* __restrict__ U3) {
    int idx = blockIdx.x * blockDim.x + threadIdx.x;
    if (idx >= NT3 * NK3) return;
    int t = idx / NK3, k = idx - t * NK3;
    int p = 0, rem = t;
    while (rem >= (II - p) * (II - p + 1) / 2) { rem -= (II - p) * (II - p + 1) / 2; p++; }
    int q = p;
    while (rem >= II - q) { rem -= II - q; q++; }
    int j = q + rem;

    float s;
    if (p == q && q == j) {
        s = U3AT(p, p, p);
    } else if (p == q) {
        s = U3AT(p, p, j) + U3AT(p, j, p) + U3AT(j, p, p);
    } else if (q == j) {
        s = U3AT(p, q, q) + U3AT(q, p, q) + U3AT(q, q, p);
    } else {
        s = U3AT(p, q, j) + U3AT(p, j, q) + U3AT(q, p, j) +
            U3AT(q, j, p) + U3AT(j, p, q) + U3AT(j, q, p);
    }
    g_P[t * NK3 + k] = s;
}

// ---------------- P1: per-channel coefficient build (padded-run layout) ----------------
__global__ void p1_kernel(const float* __restrict__ U2, const float* __restrict__ U1,
                          const float* __restrict__ w3, const float* __restrict__ w2,
                          const float* __restrict__ w1) {
    int c = blockIdx.x;
    int tid = threadIdx.x;
    __shared__ float w3s[NK3];
    __shared__ float w2s[NK2];
    __shared__ float w1s;
    if (tid < NK3) w3s[tid] = w3[c * NK3 + tid];
    if (tid < NK2) w2s[tid] = w2[c * NK2 + tid];
    if (tid == 0)  w1s = w1[c];
    __syncthreads();

    ull* cc = g_coeff + (size_t)c * CSTRIDE;

    // each thread handles one (p,q) run
    for (int r = tid; r < NT2; r += blockDim.x) {
        int p = 0, rem = r;
        while (rem >= II - p) { rem -= II - p; p++; }
        int q = p + rem;
        // compact triple start index
        int t0 = 0;
        for (int pp = 0; pp < p; pp++) t0 += (II - pp) * (II - pp + 1) / 2;
        for (int qq = p; qq < q; qq++) t0 += II - qq;
        // padded start index (even)
        int s0 = 0;
        for (int pp = 0; pp < p; pp++)
            for (int qq = pp; qq < II; qq++) s0 += (II - qq + 1) & ~1;
        for (int qq = p; qq < q; qq++) s0 += (II - qq + 1) & ~1;

        int len = II - q;
        for (int l = 0; l < len; l++) {
            float s = 0.f;
#pragma unroll
            for (int k = 0; k < NK3; k++) s += g_P[(t0 + l) * NK3 + k] * w3s[k];
            cc[s0 + l] = pk2(s, s);
        }
        if (len & 1) cc[s0 + len] = 0ull;   // pad coeff = 0

        // c2 for this run
        float s2 = 0.f;
#pragma unroll
        for (int k = 0; k < NK2; k++) {
            float v = (p == q) ? U2[(p * II + p) * NK2 + k]
                               : (U2[(p * II + q) * NK2 + k] + U2[(q * II + p) * NK2 + k]);
            s2 += w2s[k] * v;
        }
        cc[NT3P + r] = pk2(s2, s2);
    }
    for (int p = tid; p < II; p += blockDim.x) {
        float s = U1[p] * w1s;  // K1 == 1
        cc[NT3P + NT2 + p] = pk2(s, s);
    }
}

// ---------------- Main: symmetric contraction, 4 b's/thread, LDS.128 coeffs ----------------
__global__ __launch_bounds__(128, 3) void main_kernel(const float* __restrict__ nf, int B) {
    __shared__ __align__(16) ull sc[NT3P + NT2 + II];   // 1040 ull = 8320 B
    int c = blockIdx.y;
    {
        const ull* cc = g_coeff + (size_t)c * CSTRIDE;
        for (int i = threadIdx.x; i < NT3P + NT2 + II; i += blockDim.x) sc[i] = cc[i];
    }
    __syncthreads();

    int b0 = (blockIdx.x * blockDim.x + threadIdx.x) * 4;
    if (b0 >= B) return;

    const float* x0 = nf + ((size_t)b0 * CI + c) * II;
    const size_t str = (size_t)CI * II;

    ull xA[II], xB[II];
#pragma unroll
    for (int i = 0; i < II; i += 4) {
        float4 a0 = *reinterpret_cast<const float4*>(x0 + i);
        float4 a1 = *reinterpret_cast<const float4*>(x0 + str + i);
        float4 a2 = *reinterpret_cast<const float4*>(x0 + 2 * str + i);
        float4 a3 = *reinterpret_cast<const float4*>(x0 + 3 * str + i);
        xA[i + 0] = pk2(a0.x, a1.x); xA[i + 1] = pk2(a0.y, a1.y);
        xA[i + 2] = pk2(a0.z, a1.z); xA[i + 3] = pk2(a0.w, a1.w);
        xB[i + 0] = pk2(a2.x, a3.x); xB[i + 1] = pk2(a2.y, a3.y);
        xB[i + 2] = pk2(a2.z, a3.z); xB[i + 3] = pk2(a2.w, a3.w);
    }

    ull accA = 0ull, accB = 0ull;
    int s = 0, u = 0;   // constant-folded by full unroll
#pragma unroll
    for (int p = 0; p < II; p++) {
#pragma unroll
        for (int q = p; q < II; q++) {
            ull c2v = sc[NT3P + u];
            ull pA = c2v, pB = c2v;
            const int len = II - q;
            const int pairs = (len + 1) >> 1;
#pragma unroll
            for (int jj = 0; jj < pairs; jj++) {
                ulonglong2 v = *reinterpret_cast<const ulonglong2*>(&sc[s + 2 * jj]);
                const int j0 = q + 2 * jj;
                const int j1 = (2 * jj + 1 < len) ? (j0 + 1) : q;   // pad coeff is 0
                pA = fma2(xA[j0], v.x, pA);
                pB = fma2(xB[j0], v.x, pB);
                pA = fma2(xA[j1], v.y, pA);
                pB = fma2(xB[j1], v.y, pB);
            }
            ull xpqA = mul2(xA[p], xA[q]);
            ull xpqB = mul2(xB[p], xB[q]);
            accA = fma2(xpqA, pA, accA);
            accB = fma2(xpqB, pB, accB);
            s += 2 * pairs;
            u += 1;
        }
    }
#pragma unroll
    for (int p = 0; p < II; p++) {
        ull c1v = sc[NT3P + NT2 + p];
        accA = fma2(xA[p], c1v, accA);
        accB = fma2(xB[p], c1v, accB);
    }

    float r0, r1, r2, r3;
    upk2(accA, r0, r1);
    upk2(accB, r2, r3);
    g_out1[(size_t)(b0 + 0) * CI + c] = r0;
    g_out1[(size_t)(b0 + 1) * CI + c] = r1;
    g_out1[(size_t)(b0 + 2) * CI + c] = r2;
    g_out1[(size_t)(b0 + 3) * CI + c] = r3;
}

// ---------------- o3.Linear: (B,C) @ (C,C) * 1/sqrt(C), f32x2, dup-free ----------------
__global__ __launch_bounds__(256) void lin_kernel(const float* __restrict__ W,
                                                  float* __restrict__ O) {
    // A staged pre-duplicated as (a,a) ull pairs: As[m][k], 32 m x 64 k
    __shared__ __align__(16) ull  As[32][66];
    __shared__ __align__(16) float Bs[64][64];

    int mb = blockIdx.x * 32, nb = blockIdx.y * 64;
    int tid = threadIdx.x;
    int tx = tid & 15;         // n quad
    int ty = tid >> 4;         // m pair
    int m0 = mb + ty * 2;
    int n0 = nb + tx * 4;

    ull acc00 = 0ull, acc01 = 0ull, acc10 = 0ull, acc11 = 0ull;

    for (int k0 = 0; k0 < CI; k0 += 64) {
        // stage A: 32 x 64 floats, duplicated into ull pairs
#pragma unroll
        for (int i = 0; i < 2; i++) {
            int f = tid + i * 256;
            int m = f >> 4, kk = (f & 15) * 4;
            float4 v = *reinterpret_cast<const float4*>(&g_out1[(size_t)(mb + m) * CI + k0 + kk]);
            ulonglong2 w0, w1;
            w0.x = pk2(v.x, v.x); w0.y = pk2(v.y, v.y);
            w1.x = pk2(v.z, v.z); w1.y = pk2(v.w, v.w);
            *reinterpret_cast<ulonglong2*>(&As[m][kk])     = w0;
            *reinterpret_cast<ulonglong2*>(&As[m][kk + 2]) = w1;
        }
        // stage B: 64 x 64 floats
#pragma unroll
        for (int i = 0; i < 4; i++) {
            int f = tid + i * 256;
            int kk = f >> 4, n4 = (f & 15) * 4;
            *reinterpret_cast<float4*>(&Bs[kk][n4]) =
                *reinterpret_cast<const float4*>(&W[(size_t)(k0 + kk) * CI + nb + n4]);
        }
        __syncthreads();
#pragma unroll 16
        for (int kk = 0; kk < 64; kk++) {
            ull da0 = As[ty * 2 + 0][kk];
            ull da1 = As[ty * 2 + 1][kk];
            ulonglong2 bv = *reinterpret_cast<const ulonglong2*>(&Bs[kk][tx * 4]);
            acc00 = fma2(da0, bv.x, acc00);
            acc01 = fma2(da0, bv.y, acc01);
            acc10 = fma2(da1, bv.x, acc10);
            acc11 = fma2(da1, bv.y, acc11);
        }
        __syncthreads();
    }

    const float inv = 0.0625f;  // 1/sqrt(256)
    float r0, r1, r2, r3;
    upk2(acc00, r0, r1); upk2(acc01, r2, r3);
    float4 o0 = make_float4(r0 * inv, r1 * inv, r2 * inv, r3 * inv);
    *reinterpret_cast<float4*>(&O[(size_t)m0 * CI + n0]) = o0;
    upk2(acc10, r0, r1); upk2(acc11, r2, r3);
    float4 o1 = make_float4(r0 * inv, r1 * inv, r2 * inv, r3 * inv);
    *reinterpret_cast<float4*>(&O[(size_t)(m0 + 1) * CI + n0]) = o1;
}

// ---------------- launch ----------------
extern "C" void kernel_launch(void* const* d_in, const int* in_sizes, int n_in,
                              void* d_out, int out_size) {
    const float* nf = (const float*)d_in[0];
    const float* U3 = (const float*)d_in[1];
    const float* U2 = (const float*)d_in[2];
    const float* U1 = (const float*)d_in[3];
    const float* w3 = (const float*)d_in[4];
    const float* w2 = (const float*)d_in[5];
    const float* w1 = (const float*)d_in[6];
    const float* WL = (const float*)d_in[7];
    float* out = (float*)d_out;

    int B = in_sizes[0] / (CI * II);   // 4096

    p0_kernel<<<(NT3 * NK3 + 255) / 256, 256>>>(U3);
    p1_kernel<<<CI, 128>>>(U2, U1, w3, w2, w1);
    main_kernel<<<dim3((B + 511) / 512, CI), 128>>>(nf, B);
    lin_kernel<<<dim3(B / 32, CI / 64), 256>>>(WL, out);
}

// round 3
// speedup vs baseline: 1.1099x; 1.1099x over previous
#include <cuda_runtime.h>
#include <cstdint>

#define CI  256   // channels
#define II  16    // irrep dim
#define NK3 23
#define NK2 4
#define NT3 816   // C(18,3) sorted triples p<=q<=j
#define NT2 136   // sorted pairs p<=q
#define NCOEFF (NT3 + NT2 + II)   // 968
#define BMAX 4096

// ---------------- static device scratch (no allocation allowed) ----------------
__device__ float              g_P[NT3 * NK3];          // symmetrized U3 basis
__device__ unsigned long long g_coeff[CI * 1024];      // per-channel packed (v,v) coeffs
__device__ float              g_out1[BMAX * CI];       // (B, C) intermediate

typedef unsigned long long ull;

// ---------------- f32x2 packed-math helpers (sm_103a FFMA2 path) ----------------
__device__ __forceinline__ ull pk2(float lo, float hi) {
    ull r;
    asm("mov.b64 %0, {%1, %2};" : "=l"(r) : "f"(lo), "f"(hi));
    return r;
}
__device__ __forceinline__ void upk2(ull v, float& lo, float& hi) {
    asm("mov.b64 {%0, %1}, %2;" : "=f"(lo), "=f"(hi) : "l"(v));
}
__device__ __forceinline__ ull fma2(ull a, ull b, ull c) {
    ull d;
    asm("fma.rn.f32x2 %0, %1, %2, %3;" : "=l"(d) : "l"(a), "l"(b), "l"(c));
    return d;
}
__device__ __forceinline__ ull mul2(ull a, ull b) {
    ull d;
    asm("mul.rn.f32x2 %0, %1, %2;" : "=l"(d) : "l"(a), "l"(b));
    return d;
}

// ---------------- P0: symmetrize U3 over permutations -> g_P[t][k] ----------------
#define U3AT(a, b, d) U3[((((a) * II + (b)) * II + (d)) * NK3) + k]

__global__ void p0_kernel(const float* __restrict__ U3) {
    int idx = blockIdx.x * blockDim.x + threadIdx.x;
    if (idx >= NT3 * NK3) return;
    int t = idx / NK3, k = idx - t * NK3;
    int p = 0, rem = t;
    while (rem >= (II - p) * (II - p + 1) / 2) { rem -= (II - p) * (II - p + 1) / 2; p++; }
    int q = p;
    while (rem >= II - q) { rem -= II - q; q++; }
    int j = q + rem;

    float s;
    if (p == q && q == j) {
        s = U3AT(p, p, p);
    } else if (p == q) {
        s = U3AT(p, p, j) + U3AT(p, j, p) + U3AT(j, p, p);
    } else if (q == j) {
        s = U3AT(p, q, q) + U3AT(q, p, q) + U3AT(q, q, p);
    } else {
        s = U3AT(p, q, j) + U3AT(p, j, q) + U3AT(q, p, j) +
            U3AT(q, j, p) + U3AT(j, p, q) + U3AT(j, q, p);
    }
    g_P[t * NK3 + k] = s;
}

// ---------------- P1: per-channel coefficient build (compact layout) ----------------
__global__ void p1_kernel(const float* __restrict__ U2, const float* __restrict__ U1,
                          const float* __restrict__ w3, const float* __restrict__ w2,
                          const float* __restrict__ w1) {
    int c = blockIdx.x;
    int tid = threadIdx.x;
    __shared__ float w3s[NK3];
    __shared__ float w2s[NK2];
    __shared__ float w1s;
    if (tid < NK3) w3s[tid] = w3[c * NK3 + tid];
    if (tid < NK2) w2s[tid] = w2[c * NK2 + tid];
    if (tid == 0)  w1s = w1[c];
    __syncthreads();

    ull* cc = g_coeff + (size_t)c * 1024;

    for (int t = tid; t < NT3; t += blockDim.x) {
        float s = 0.f;
#pragma unroll
        for (int k = 0; k < NK3; k++) s += g_P[t * NK3 + k] * w3s[k];
        cc[t] = pk2(s, s);
    }
    for (int u = tid; u < NT2; u += blockDim.x) {
        int p = 0, rem = u;
        while (rem >= II - p) { rem -= II - p; p++; }
        int q = p + rem;
        float s = 0.f;
#pragma unroll
        for (int k = 0; k < NK2; k++) {
            float v = (p == q) ? U2[(p * II + p) * NK2 + k]
                               : (U2[(p * II + q) * NK2 + k] + U2[(q * II + p) * NK2 + k]);
            s += w2s[k] * v;
        }
        cc[NT3 + u] = pk2(s, s);
    }
    for (int p = tid; p < II; p += blockDim.x) {
        float s = U1[p] * w1s;  // K1 == 1
        cc[NT3 + NT2 + p] = pk2(s, s);
    }
}

// ---------------- Main: symmetric contraction, 4 b's per thread, f32x2 math ----------------
__global__ __launch_bounds__(128, 4) void main_kernel(const float* __restrict__ nf, int B) {
    __shared__ ull sco[NCOEFF];
    int c = blockIdx.y;
    const ull* cc = g_coeff + (size_t)c * 1024;
    for (int i = threadIdx.x; i < NCOEFF; i += blockDim.x) sco[i] = cc[i];
    __syncthreads();

    int b0 = (blockIdx.x * blockDim.x + threadIdx.x) * 4;
    if (b0 >= B) return;

    const float* x0 = nf + ((size_t)b0 * CI + c) * II;
    const size_t str = (size_t)CI * II;

    ull xA[II], xB[II];
#pragma unroll
    for (int i = 0; i < II; i += 4) {
        float4 a0 = *reinterpret_cast<const float4*>(x0 + i);
        float4 a1 = *reinterpret_cast<const float4*>(x0 + str + i);
        float4 a2 = *reinterpret_cast<const float4*>(x0 + 2 * str + i);
        float4 a3 = *reinterpret_cast<const float4*>(x0 + 3 * str + i);
        xA[i + 0] = pk2(a0.x, a1.x); xA[i + 1] = pk2(a0.y, a1.y);
        xA[i + 2] = pk2(a0.z, a1.z); xA[i + 3] = pk2(a0.w, a1.w);
        xB[i + 0] = pk2(a2.x, a3.x); xB[i + 1] = pk2(a2.y, a3.y);
        xB[i + 2] = pk2(a2.z, a3.z); xB[i + 3] = pk2(a2.w, a3.w);
    }

    ull accA = 0ull, accB = 0ull;   // packed (0.f, 0.f)
    int t = 0, u = 0;               // constant-folded by full unroll
#pragma unroll
    for (int p = 0; p < II; p++) {
#pragma unroll
        for (int q = p; q < II; q++) {
            ull c2v = sco[NT3 + u]; u++;
            ull pA = c2v, pB = c2v;
#pragma unroll
            for (int j = q; j < II; j++) {
                ull sv = sco[t]; t++;
                pA = fma2(xA[j], sv, pA);
                pB = fma2(xB[j], sv, pB);
            }
            ull xpqA = mul2(xA[p], xA[q]);
            ull xpqB = mul2(xB[p], xB[q]);
            accA = fma2(xpqA, pA, accA);
            accB = fma2(xpqB, pB, accB);
        }
    }
#pragma unroll
    for (int p = 0; p < II; p++) {
        ull c1v = sco[NT3 + NT2 + p];
        accA = fma2(xA[p], c1v, accA);
        accB = fma2(xB[p], c1v, accB);
    }

    float r0, r1, r2, r3;
    upk2(accA, r0, r1);
    upk2(accB, r2, r3);
    g_out1[(size_t)(b0 + 0) * CI + c] = r0;
    g_out1[(size_t)(b0 + 1) * CI + c] = r1;
    g_out1[(size_t)(b0 + 2) * CI + c] = r2;
    g_out1[(size_t)(b0 + 3) * CI + c] = r3;
}

// ---------------- o3.Linear: 64x64 block tile, 4m x 8n per thread, f32x2 ----------------
__global__ __launch_bounds__(128) void lin_kernel(const float* __restrict__ W,
                                                  float* __restrict__ O) {
    __shared__ __align__(16) ull   As[64][66];   // [kk][m], pre-duplicated (a,a)
    __shared__ __align__(16) float Bs[64][68];   // [kk][n]

    int mb = blockIdx.x * 64, nb = blockIdx.y * 64;
    int tid = threadIdx.x;
    int tx = tid & 7;       // n octet   (8 tx)
    int ty = tid >> 3;      // m quad    (16 ty)

    ull acc[4][4] = {};     // [mi][n-pair]

    for (int k0 = 0; k0 < CI; k0 += 64) {
        // stage A: 64m x 64k floats of g_out1, transposed + duplicated
#pragma unroll
        for (int i = 0; i < 8; i++) {
            int f = tid + i * 128;                 // 0..1023 float4 slots
            int m = f & 63, kk = (f >> 6) * 4;     // kk in {0,4,...,60}
            float4 v = *reinterpret_cast<const float4*>(
                &g_out1[(size_t)(mb + m) * CI + k0 + kk]);
            As[kk + 0][m] = pk2(v.x, v.x);
            As[kk + 1][m] = pk2(v.y, v.y);
            As[kk + 2][m] = pk2(v.z, v.z);
            As[kk + 3][m] = pk2(v.w, v.w);
        }
        // stage B: 64k x 64n floats of W (coalesced)
#pragma unroll
        for (int i = 0; i < 8; i++) {
            int f = tid + i * 128;
            int kk = f >> 4, n4 = (f & 15) * 4;
            *reinterpret_cast<float4*>(&Bs[kk][n4]) =
                *reinterpret_cast<const float4*>(&W[(size_t)(k0 + kk) * CI + nb + n4]);
        }
        __syncthreads();
#pragma unroll 8
        for (int kk = 0; kk < 64; kk++) {
            ulonglong2 a01 = *reinterpret_cast<const ulonglong2*>(&As[kk][ty * 4]);
            ulonglong2 a23 = *reinterpret_cast<const ulonglong2*>(&As[kk][ty * 4 + 2]);
            ulonglong2 b01 = *reinterpret_cast<const ulonglong2*>(&Bs[kk][tx * 8]);
            ulonglong2 b23 = *reinterpret_cast<const ulonglong2*>(&Bs[kk][tx * 8 + 4]);
            acc[0][0] = fma2(a01.x, b01.x, acc[0][0]);
            acc[0][1] = fma2(a01.x, b01.y, acc[0][1]);
            acc[0][2] = fma2(a01.x, b23.x, acc[0][2]);
            acc[0][3] = fma2(a01.x, b23.y, acc[0][3]);
            acc[1][0] = fma2(a01.y, b01.x, acc[1][0]);
            acc[1][1] = fma2(a01.y, b01.y, acc[1][1]);
            acc[1][2] = fma2(a01.y, b23.x, acc[1][2]);
            acc[1][3] = fma2(a01.y, b23.y, acc[1][3]);
            acc[2][0] = fma2(a23.x, b01.x, acc[2][0]);
            acc[2][1] = fma2(a23.x, b01.y, acc[2][1]);
            acc[2][2] = fma2(a23.x, b23.x, acc[2][2]);
            acc[2][3] = fma2(a23.x, b23.y, acc[2][3]);
            acc[3][0] = fma2(a23.y, b01.x, acc[3][0]);
            acc[3][1] = fma2(a23.y, b01.y, acc[3][1]);
            acc[3][2] = fma2(a23.y, b23.x, acc[3][2]);
            acc[3][3] = fma2(a23.y, b23.y, acc[3][3]);
        }
        __syncthreads();
    }

    const float inv = 0.0625f;  // 1/sqrt(256)
#pragma unroll
    for (int i = 0; i < 4; i++) {
        float r[8];
#pragma unroll
        for (int j = 0; j < 4; j++) {
            upk2(acc[i][j], r[2 * j], r[2 * j + 1]);
            r[2 * j] *= inv; r[2 * j + 1] *= inv;
        }
        float* o = &O[(size_t)(mb + ty * 4 + i) * CI + nb + tx * 8];
        *reinterpret_cast<float4*>(o)     = make_float4(r[0], r[1], r[2], r[3]);
        *reinterpret_cast<float4*>(o + 4) = make_float4(r[4], r[5], r[6], r[7]);
    }
}

// ---------------- launch ----------------
extern "C" void kernel_launch(void* const* d_in, const int* in_sizes, int n_in,
                              void* d_out, int out_size) {
    const float* nf = (const float*)d_in[0];
    const float* U3 = (const float*)d_in[1];
    const float* U2 = (const float*)d_in[2];
    const float* U1 = (const float*)d_in[3];
    const float* w3 = (const float*)d_in[4];
    const float* w2 = (const float*)d_in[5];
    const float* w1 = (const float*)d_in[6];
    const float* WL = (const float*)d_in[7];
    float* out = (float*)d_out;

    int B = in_sizes[0] / (CI * II);   // 4096

    p0_kernel<<<(NT3 * NK3 + 255) / 256, 256>>>(U3);
    p1_kernel<<<CI, 128>>>(U2, U1, w3, w2, w1);
    main_kernel<<<dim3((B + 511) / 512, CI), 128>>>(nf, B);
    lin_kernel<<<dim3(B / 64, CI / 64), 128>>>(WL, out);
}

// round 4
// speedup vs baseline: 1.4631x; 1.3182x over previous
#include <cuda_runtime.h>
#include <cstdint>

#define CI  256   // channels
#define II  16    // irrep dim
#define NK3 23
#define NK2 4
#define NT3 816   // C(18,3) sorted triples p<=q<=j
#define NT2 136   // sorted pairs p<=q
#define NCOEFF (NT3 + NT2 + II)   // 968
#define BMAX 4096

// ---------------- static device scratch (no allocation allowed) ----------------
__device__ float              g_P[NT3 * NK3];          // symmetrized U3 basis
__device__ unsigned long long g_coeff[CI * 1024];      // per-channel packed (v,v) coeffs
__device__ float              g_out1T[CI * BMAX];      // (C, B) transposed intermediate

typedef unsigned long long ull;

// ---------------- f32x2 packed-math helpers (sm_103a FFMA2 path) ----------------
__device__ __forceinline__ ull pk2(float lo, float hi) {
    ull r;
    asm("mov.b64 %0, {%1, %2};" : "=l"(r) : "f"(lo), "f"(hi));
    return r;
}
__device__ __forceinline__ void upk2(ull v, float& lo, float& hi) {
    asm("mov.b64 {%0, %1}, %2;" : "=f"(lo), "=f"(hi) : "l"(v));
}
__device__ __forceinline__ ull fma2(ull a, ull b, ull c) {
    ull d;
    asm("fma.rn.f32x2 %0, %1, %2, %3;" : "=l"(d) : "l"(a), "l"(b), "l"(c));
    return d;
}

// ---------------- P0: symmetrize U3 over permutations -> g_P[t][k] ----------------
#define U3AT(a, b, d) U3[((((a) * II + (b)) * II + (d)) * NK3) + k]

__global__ void p0_kernel(const float* __restrict__ U3) {
    int idx = blockIdx.x * blockDim.x + threadIdx.x;
    if (idx >= NT3 * NK3) return;
    int t = idx / NK3, k = idx - t * NK3;
    int p = 0, rem = t;
    while (rem >= (II - p) * (II - p + 1) / 2) { rem -= (II - p) * (II - p + 1) / 2; p++; }
    int q = p;
    while (rem >= II - q) { rem -= II - q; q++; }
    int j = q + rem;

    float s;
    if (p == q && q == j) {
        s = U3AT(p, p, p);
    } else if (p == q) {
        s = U3AT(p, p, j) + U3AT(p, j, p) + U3AT(j, p, p);
    } else if (q == j) {
        s = U3AT(p, q, q) + U3AT(q, p, q) + U3AT(q, q, p);
    } else {
        s = U3AT(p, q, j) + U3AT(p, j, q) + U3AT(q, p, j) +
            U3AT(q, j, p) + U3AT(j, p, q) + U3AT(j, q, p);
    }
    g_P[t * NK3 + k] = s;
}

// ---------------- P1: per-channel coefficient build ----------------
__global__ void p1_kernel(const float* __restrict__ U2, const float* __restrict__ U1,
                          const float* __restrict__ w3, const float* __restrict__ w2,
                          const float* __restrict__ w1) {
    int c = blockIdx.x;
    int tid = threadIdx.x;
    __shared__ float w3s[NK3];
    __shared__ float w2s[NK2];
    __shared__ float w1s;
    if (tid < NK3) w3s[tid] = w3[c * NK3 + tid];
    if (tid < NK2) w2s[tid] = w2[c * NK2 + tid];
    if (tid == 0)  w1s = w1[c];
    __syncthreads();

    ull* cc = g_coeff + (size_t)c * 1024;

    for (int t = tid; t < NT3; t += blockDim.x) {
        float s = 0.f;
#pragma unroll
        for (int k = 0; k < NK3; k++) s += g_P[t * NK3 + k] * w3s[k];
        cc[t] = pk2(s, s);
    }
    for (int u = tid; u < NT2; u += blockDim.x) {
        int p = 0, rem = u;
        while (rem >= II - p) { rem -= II - p; p++; }
        int q = p + rem;
        float s = 0.f;
#pragma unroll
        for (int k = 0; k < NK2; k++) {
            float v = (p == q) ? U2[(p * II + p) * NK2 + k]
                               : (U2[(p * II + q) * NK2 + k] + U2[(q * II + p) * NK2 + k]);
            s += w2s[k] * v;
        }
        cc[NT3 + u] = pk2(s, s);
    }
    for (int p = tid; p < II; p += blockDim.x) {
        float s = U1[p] * w1s;  // K1 == 1
        cc[NT3 + NT2 + p] = pk2(s, s);
    }
}

// ---------------- Main: factored symmetric contraction, staged x, 4 b's/thread ----------------
#define XPAD 524   // row stride (floats): mult of 4 for 16B align, odd/32-friendly
__global__ __launch_bounds__(128, 4) void main_kernel(const float* __restrict__ nf) {
    __shared__ ull   sco[NCOEFF];           // 7.75 KB
    __shared__ float xs[II][XPAD];          // 33.5 KB transposed x tile (512 b's)
    int c = blockIdx.y;
    int tid = threadIdx.x;
    {
        const ull* cc = g_coeff + (size_t)c * 1024;
        for (int i = tid; i < NCOEFF; i += 128) sco[i] = cc[i];
    }
    int bbase = blockIdx.x * 512;

    // cooperative coalesced load of x tile: 512 rows x 16 floats, transposed into xs[i][r]
#pragma unroll
    for (int it = 0; it < 16; it++) {
        int f = it * 128 + tid;
        int r = f >> 2, qd = f & 3;
        float4 v = *reinterpret_cast<const float4*>(
            &nf[((size_t)(bbase + r) * CI + c) * II + qd * 4]);
        xs[qd * 4 + 0][r] = v.x;
        xs[qd * 4 + 1][r] = v.y;
        xs[qd * 4 + 2][r] = v.z;
        xs[qd * 4 + 3][r] = v.w;
    }
    __syncthreads();

    // per-thread x: 4 consecutive b's, packed as f32x2 pairs (A = b0,b1; B = b2,b3)
    int t4 = tid * 4;
    ull xA[II], xB[II];
#pragma unroll
    for (int i = 0; i < II; i++) {
        float4 v = *reinterpret_cast<const float4*>(&xs[i][t4]);
        xA[i] = pk2(v.x, v.y);
        xB[i] = pk2(v.z, v.w);
    }

    // out = sum_p x_p * ( c1_p + sum_{q>=p} x_q * ( c2_pq + sum_{j>=q} c3_pqj x_j ) )
    ull accA = 0ull, accB = 0ull;
    int s = 0, u = 0;     // constant-folded by full unroll
#pragma unroll
    for (int p = 0; p < II; p++) {
        ull c1v = sco[NT3 + NT2 + p];
        ull innerA = c1v, innerB = c1v;
#pragma unroll
        for (int q = p; q < II; q++) {
            ull c2v = sco[NT3 + u]; u++;
            ull pA = c2v, pB = c2v;
#pragma unroll
            for (int j = q; j < II; j++) {
                ull sv = sco[s]; s++;
                pA = fma2(xA[j], sv, pA);
                pB = fma2(xB[j], sv, pB);
            }
            innerA = fma2(xA[q], pA, innerA);
            innerB = fma2(xB[q], pB, innerB);
        }
        accA = fma2(xA[p], innerA, accA);
        accB = fma2(xB[p], innerB, accB);
    }

    // coalesced transposed store: g_out1T[c][bbase + 4*tid .. +3]
    float r0, r1, r2, r3;
    upk2(accA, r0, r1);
    upk2(accB, r2, r3);
    *reinterpret_cast<float4*>(&g_out1T[(size_t)c * BMAX + bbase + t4]) =
        make_float4(r0, r1, r2, r3);
}

// ---------------- o3.Linear: A^T = g_out1T (K x M), 32m x 64n tiles, high occupancy ----------------
__global__ __launch_bounds__(128) void lin_kernel(const float* __restrict__ W,
                                                  float* __restrict__ O) {
    __shared__ __align__(16) ull   As[32][34];   // [kk][m] dup (a,a) pairs, 8.5 KB
    __shared__ __align__(16) float Bs[32][68];   // [kk][n], 8.7 KB

    int mb = blockIdx.x * 32, nb = blockIdx.y * 64;
    int tid = threadIdx.x;
    int tx = tid & 7;       // n octet (8)
    int ty = tid >> 3;      // m pair  (16)

    ull acc[2][4] = {};

    for (int k0 = 0; k0 < CI; k0 += 32) {
        // stage A: 32k x 32m from transposed intermediate (coalesced along m)
#pragma unroll
        for (int i = 0; i < 2; i++) {
            int f = tid + i * 128;
            int kk = f >> 3, m4 = (f & 7) * 4;
            float4 v = *reinterpret_cast<const float4*>(
                &g_out1T[(size_t)(k0 + kk) * BMAX + mb + m4]);
            As[kk][m4 + 0] = pk2(v.x, v.x);
            As[kk][m4 + 1] = pk2(v.y, v.y);
            As[kk][m4 + 2] = pk2(v.z, v.z);
            As[kk][m4 + 3] = pk2(v.w, v.w);
        }
        // stage B: 32k x 64n of W (coalesced)
#pragma unroll
        for (int i = 0; i < 4; i++) {
            int f = tid + i * 128;
            int kk = f >> 4, n4 = (f & 15) * 4;
            *reinterpret_cast<float4*>(&Bs[kk][n4]) =
                *reinterpret_cast<const float4*>(&W[(size_t)(k0 + kk) * CI + nb + n4]);
        }
        __syncthreads();
#pragma unroll
        for (int kk = 0; kk < 32; kk++) {
            ulonglong2 a  = *reinterpret_cast<const ulonglong2*>(&As[kk][ty * 2]);
            ulonglong2 b0 = *reinterpret_cast<const ulonglong2*>(&Bs[kk][tx * 8]);
            ulonglong2 b1 = *reinterpret_cast<const ulonglong2*>(&Bs[kk][tx * 8 + 4]);
            acc[0][0] = fma2(a.x, b0.x, acc[0][0]);
            acc[0][1] = fma2(a.x, b0.y, acc[0][1]);
            acc[0][2] = fma2(a.x, b1.x, acc[0][2]);
            acc[0][3] = fma2(a.x, b1.y, acc[0][3]);
            acc[1][0] = fma2(a.y, b0.x, acc[1][0]);
            acc[1][1] = fma2(a.y, b0.y, acc[1][1]);
            acc[1][2] = fma2(a.y, b1.x, acc[1][2]);
            acc[1][3] = fma2(a.y, b1.y, acc[1][3]);
        }
        __syncthreads();
    }

    const float inv = 0.0625f;  // 1/sqrt(256)
#pragma unroll
    for (int mi = 0; mi < 2; mi++) {
        float r[8];
#pragma unroll
        for (int j = 0; j < 4; j++) {
            upk2(acc[mi][j], r[2 * j], r[2 * j + 1]);
            r[2 * j] *= inv; r[2 * j + 1] *= inv;
        }
        float* o = &O[(size_t)(mb + ty * 2 + mi) * CI + nb + tx * 8];
        *reinterpret_cast<float4*>(o)     = make_float4(r[0], r[1], r[2], r[3]);
        *reinterpret_cast<float4*>(o + 4) = make_float4(r[4], r[5], r[6], r[7]);
    }
}

// ---------------- launch ----------------
extern "C" void kernel_launch(void* const* d_in, const int* in_sizes, int n_in,
                              void* d_out, int out_size) {
    const float* nf = (const float*)d_in[0];
    const float* U3 = (const float*)d_in[1];
    const float* U2 = (const float*)d_in[2];
    const float* U1 = (const float*)d_in[3];
    const float* w3 = (const float*)d_in[4];
    const float* w2 = (const float*)d_in[5];
    const float* w1 = (const float*)d_in[6];
    const float* WL = (const float*)d_in[7];
    float* out = (float*)d_out;

    int B = in_sizes[0] / (CI * II);   // 4096

    p0_kernel<<<(NT3 * NK3 + 255) / 256, 256>>>(U3);
    p1_kernel<<<CI, 128>>>(U2, U1, w3, w2, w1);
    main_kernel<<<dim3(B / 512, CI), 128>>>(nf);
    lin_kernel<<<dim3(B / 32, CI / 64), 128>>>(WL, out);
}

// round 5
// speedup vs baseline: 1.5648x; 1.0695x over previous
#include <cuda_runtime.h>
#include <cstdint>

#define CI  256   // channels
#define II  16    // irrep dim
#define NK3 23
#define NK2 4
#define NT3 816   // C(18,3) sorted triples p<=q<=j
#define NT2 136   // sorted pairs p<=q
#define NCOEFF (NT3 + NT2 + II)   // 968
#define BMAX 4096

// ---------------- static device scratch (no allocation allowed) ----------------
__device__ float              g_P[NT3 * NK3];          // symmetrized U3 basis
__device__ unsigned long long g_coeff[CI * 1024];      // per-channel packed (v,v) coeffs
__device__ float              g_out1T[CI * BMAX];      // (C, B) transposed intermediate

typedef unsigned long long ull;

// ---------------- f32x2 packed-math helpers (sm_103a FFMA2 path) ----------------
__device__ __forceinline__ ull pk2(float lo, float hi) {
    ull r;
    asm("mov.b64 %0, {%1, %2};" : "=l"(r) : "f"(lo), "f"(hi));
    return r;
}
__device__ __forceinline__ void upk2(ull v, float& lo, float& hi) {
    asm("mov.b64 {%0, %1}, %2;" : "=f"(lo), "=f"(hi) : "l"(v));
}
__device__ __forceinline__ ull fma2(ull a, ull b, ull c) {
    ull d;
    asm("fma.rn.f32x2 %0, %1, %2, %3;" : "=l"(d) : "l"(a), "l"(b), "l"(c));
    return d;
}
__device__ __forceinline__ ull add2(ull a, ull b) {
    ull d;
    asm("add.rn.f32x2 %0, %1, %2;" : "=l"(d) : "l"(a), "l"(b));
    return d;
}

// ---------------- P0: symmetrize U3 over permutations -> g_P[t][k] ----------------
#define U3AT(a, b, d) U3[((((a) * II + (b)) * II + (d)) * NK3) + k]

__global__ void p0_kernel(const float* __restrict__ U3) {
    int idx = blockIdx.x * blockDim.x + threadIdx.x;
    if (idx >= NT3 * NK3) return;
    int t = idx / NK3, k = idx - t * NK3;
    int p = 0, rem = t;
    while (rem >= (II - p) * (II - p + 1) / 2) { rem -= (II - p) * (II - p + 1) / 2; p++; }
    int q = p;
    while (rem >= II - q) { rem -= II - q; q++; }
    int j = q + rem;

    float s;
    if (p == q && q == j) {
        s = U3AT(p, p, p);
    } else if (p == q) {
        s = U3AT(p, p, j) + U3AT(p, j, p) + U3AT(j, p, p);
    } else if (q == j) {
        s = U3AT(p, q, q) + U3AT(q, p, q) + U3AT(q, q, p);
    } else {
        s = U3AT(p, q, j) + U3AT(p, j, q) + U3AT(q, p, j) +
            U3AT(q, j, p) + U3AT(j, p, q) + U3AT(j, q, p);
    }
    g_P[t * NK3 + k] = s;
}

// ---------------- P1: per-channel coefficient build ----------------
__global__ void p1_kernel(const float* __restrict__ U2, const float* __restrict__ U1,
                          const float* __restrict__ w3, const float* __restrict__ w2,
                          const float* __restrict__ w1) {
    int c = blockIdx.x;
    int tid = threadIdx.x;
    __shared__ float w3s[NK3];
    __shared__ float w2s[NK2];
    __shared__ float w1s;
    if (tid < NK3) w3s[tid] = w3[c * NK3 + tid];
    if (tid < NK2) w2s[tid] = w2[c * NK2 + tid];
    if (tid == 0)  w1s = w1[c];
    __syncthreads();

    ull* cc = g_coeff + (size_t)c * 1024;

    for (int t = tid; t < NT3; t += blockDim.x) {
        float s = 0.f;
#pragma unroll
        for (int k = 0; k < NK3; k++) s += g_P[t * NK3 + k] * w3s[k];
        cc[t] = pk2(s, s);
    }
    for (int u = tid; u < NT2; u += blockDim.x) {
        int p = 0, rem = u;
        while (rem >= II - p) { rem -= II - p; p++; }
        int q = p + rem;
        float s = 0.f;
#pragma unroll
        for (int k = 0; k < NK2; k++) {
            float v = (p == q) ? U2[(p * II + p) * NK2 + k]
                               : (U2[(p * II + q) * NK2 + k] + U2[(q * II + p) * NK2 + k]);
            s += w2s[k] * v;
        }
        cc[NT3 + u] = pk2(s, s);
    }
    for (int p = tid; p < II; p += blockDim.x) {
        float s = U1[p] * w1s;  // K1 == 1
        cc[NT3 + NT2 + p] = pk2(s, s);
    }
}

// ---------------- Main: factored symmetric contraction, staged x, 4 b's/thread ----------------
#define XPAD 524   // row stride (floats): mult of 4 for 16B align
__global__ __launch_bounds__(128, 4) void main_kernel(const float* __restrict__ nf) {
    __shared__ ull   sco[NCOEFF];           // 7.75 KB
    __shared__ float xs[II][XPAD];          // 33.5 KB transposed x tile (512 b's)
    int c = blockIdx.y;
    int tid = threadIdx.x;
    {
        const ull* cc = g_coeff + (size_t)c * 1024;
        for (int i = tid; i < NCOEFF; i += 128) sco[i] = cc[i];
    }
    int bbase = blockIdx.x * 512;

    // cooperative load of x tile: 512 rows x 16 floats, transposed into xs[i][r]
#pragma unroll
    for (int it = 0; it < 16; it++) {
        int f = it * 128 + tid;
        int r = f >> 2, qd = f & 3;
        float4 v = *reinterpret_cast<const float4*>(
            &nf[((size_t)(bbase + r) * CI + c) * II + qd * 4]);
        xs[qd * 4 + 0][r] = v.x;
        xs[qd * 4 + 1][r] = v.y;
        xs[qd * 4 + 2][r] = v.z;
        xs[qd * 4 + 3][r] = v.w;
    }
    __syncthreads();

    // per-thread x: 4 consecutive b's, packed as f32x2 pairs (A = b0,b1; B = b2,b3)
    int t4 = tid * 4;
    ull xA[II], xB[II];
#pragma unroll
    for (int i = 0; i < II; i++) {
        float4 v = *reinterpret_cast<const float4*>(&xs[i][t4]);
        xA[i] = pk2(v.x, v.y);
        xB[i] = pk2(v.z, v.w);
    }

    // out = sum_p x_p * ( c1_p + sum_{q>=p} x_q * ( c2_pq + sum_{j>=q} c3_pqj x_j ) )
    // inner j-sum split into even/odd partial chains for 4-way FMA ILP
    ull accA = 0ull, accB = 0ull;
    int s = 0, u = 0;     // constant-folded by full unroll
#pragma unroll
    for (int p = 0; p < II; p++) {
        ull c1v = sco[NT3 + NT2 + p];
        ull innerA = c1v, innerB = c1v;
#pragma unroll
        for (int q = p; q < II; q++) {
            ull c2v = sco[NT3 + u]; u++;
            const int len = II - q;
            ull pA0 = c2v,  pB0 = c2v;
            ull pA1 = 0ull, pB1 = 0ull;
#pragma unroll
            for (int jj = 0; jj < len; jj++) {
                ull sv = sco[s]; s++;
                const int j = q + jj;
                if (jj & 1) {
                    pA1 = fma2(xA[j], sv, pA1);
                    pB1 = fma2(xB[j], sv, pB1);
                } else {
                    pA0 = fma2(xA[j], sv, pA0);
                    pB0 = fma2(xB[j], sv, pB0);
                }
            }
            ull pA = (len > 1) ? add2(pA0, pA1) : pA0;
            ull pB = (len > 1) ? add2(pB0, pB1) : pB0;
            innerA = fma2(xA[q], pA, innerA);
            innerB = fma2(xB[q], pB, innerB);
        }
        accA = fma2(xA[p], innerA, accA);
        accB = fma2(xB[p], innerB, accB);
    }

    // coalesced transposed store: g_out1T[c][bbase + 4*tid .. +3]
    float r0, r1, r2, r3;
    upk2(accA, r0, r1);
    upk2(accB, r2, r3);
    *reinterpret_cast<float4*>(&g_out1T[(size_t)c * BMAX + bbase + t4]) =
        make_float4(r0, r1, r2, r3);
}

// ---------------- o3.Linear: 32m x 32n tiles, k-stage 64, high warp count ----------------
__global__ __launch_bounds__(128) void lin_kernel(const float* __restrict__ W,
                                                  float* __restrict__ O) {
    __shared__ __align__(16) ull   As[64][34];   // [kk][m] dup (a,a) pairs, 17.4 KB
    __shared__ __align__(16) float Bs[64][36];   // [kk][n],  9.2 KB

    int mb = blockIdx.x * 32, nb = blockIdx.y * 32;
    int tid = threadIdx.x;
    int tx = tid & 7;       // n quad (8)
    int ty = tid >> 3;      // m pair (16)

    ull acc[2][2] = {};     // [mi][n-pair]

    for (int k0 = 0; k0 < CI; k0 += 64) {
        // stage A: 64k x 32m from transposed intermediate (coalesced along m)
#pragma unroll
        for (int i = 0; i < 4; i++) {
            int f = tid + i * 128;
            int kk = f >> 3, m4 = (f & 7) * 4;
            float4 v = *reinterpret_cast<const float4*>(
                &g_out1T[(size_t)(k0 + kk) * BMAX + mb + m4]);
            As[kk][m4 + 0] = pk2(v.x, v.x);
            As[kk][m4 + 1] = pk2(v.y, v.y);
            As[kk][m4 + 2] = pk2(v.z, v.z);
            As[kk][m4 + 3] = pk2(v.w, v.w);
        }
        // stage B: 64k x 32n of W (coalesced)
#pragma unroll
        for (int i = 0; i < 4; i++) {
            int f = tid + i * 128;
            int kk = f >> 3, n4 = (f & 7) * 4;
            *reinterpret_cast<float4*>(&Bs[kk][n4]) =
                *reinterpret_cast<const float4*>(&W[(size_t)(k0 + kk) * CI + nb + n4]);
        }
        __syncthreads();
#pragma unroll
        for (int kk = 0; kk < 64; kk++) {
            ulonglong2 a = *reinterpret_cast<const ulonglong2*>(&As[kk][ty * 2]);
            ulonglong2 b = *reinterpret_cast<const ulonglong2*>(
                reinterpret_cast<const char*>(&Bs[kk][tx * 4]));
            acc[0][0] = fma2(a.x, b.x, acc[0][0]);
            acc[0][1] = fma2(a.x, b.y, acc[0][1]);
            acc[1][0] = fma2(a.y, b.x, acc[1][0]);
            acc[1][1] = fma2(a.y, b.y, acc[1][1]);
        }
        __syncthreads();
    }

    const float inv = 0.0625f;  // 1/sqrt(256)
#pragma unroll
    for (int mi = 0; mi < 2; mi++) {
        float r[4];
        upk2(acc[mi][0], r[0], r[1]);
        upk2(acc[mi][1], r[2], r[3]);
        float* o = &O[(size_t)(mb + ty * 2 + mi) * CI + nb + tx * 4];
        *reinterpret_cast<float4*>(o) =
            make_float4(r[0] * inv, r[1] * inv, r[2] * inv, r[3] * inv);
    }
}

// ---------------- launch ----------------
extern "C" void kernel_launch(void* const* d_in, const int* in_sizes, int n_in,
                              void* d_out, int out_size) {
    const float* nf = (const float*)d_in[0];
    const float* U3 = (const float*)d_in[1];
    const float* U2 = (const float*)d_in[2];
    const float* U1 = (const float*)d_in[3];
    const float* w3 = (const float*)d_in[4];
    const float* w2 = (const float*)d_in[5];
    const float* w1 = (const float*)d_in[6];
    const float* WL = (const float*)d_in[7];
    float* out = (float*)d_out;

    int B = in_sizes[0] / (CI * II);   // 4096

    p0_kernel<<<(NT3 * NK3 + 255) / 256, 256>>>(U3);
    p1_kernel<<<CI, 128>>>(U2, U1, w3, w2, w1);
    main_kernel<<<dim3(B / 512, CI), 128>>>(nf);
    lin_kernel<<<dim3(B / 32, CI / 32), 128>>>(WL, out);
}